// round 1
// baseline (speedup 1.0000x reference)
#include <cuda_runtime.h>
#include <math.h>

#define B_    256
#define DV_   2048
#define WH_   196
#define DA_   620
#define DATT_ 1200
#define DOUT_ 1024
#define M_    (B_*WH_)   // 50176 = 392*128
#define CPAD  1280       // DATT padded to 10*128
#define NKT   10         // k tiles of 128

// ---- device scratch (no allocs allowed) ----
__device__ float g_xavec[B_*DA_];     // gathered answer embeddings [256][620]
__device__ float g_c[B_*CPAD];        // x_a * w_att, zero-padded    [256][1280]
__device__ float g_lpart[NKT*M_];     // per-ktile logit partials
__device__ float g_xvatt[B_*DV_];     // attention-weighted visual   [256][2048]

// ============================================================
// Kernel 1: gather embeddings + zero-pad g_c tail columns
// ============================================================
__global__ __launch_bounds__(256) void init_kernel(
    const float* __restrict__ emb, const int* __restrict__ ia)
{
    int gid = blockIdx.x * 256 + threadIdx.x;
    if (gid < B_*DA_) {
        int b = gid / DA_;
        int j = gid - b * DA_;
        g_xavec[gid] = emb[(size_t)ia[b] * DA_ + j];
    }
    if (gid < B_*(CPAD-DATT_)) {
        int b = gid / (CPAD-DATT_);
        int j = gid - b * (CPAD-DATT_);
        g_c[b*CPAD + DATT_ + j] = 0.f;
    }
}

// ============================================================
// Kernel 2/5/6: small GEMM  out[b][ko] = X[b,:J] . Wm[ko,:J]
// block = 16 batches x 32 ko (8 warps x 4 ko each)
// xsel: 0 -> g_xavec (J=620), 1 -> g_xvatt (J=2048)
// mode: 0 -> g_c = relu(acc+bias)*watt   1 -> out = acc+bias
// ============================================================
__global__ __launch_bounds__(256) void small_gemm(
    int xsel, int J,
    const float* __restrict__ Wm, int KO,
    const float* __restrict__ bias,
    const float* __restrict__ watt,
    float* __restrict__ outp, int ostride, int mode)
{
    const float* X = xsel ? g_xvatt : g_xavec;
    int t = threadIdx.x, lane = t & 31, w = t >> 5;
    int b0  = blockIdx.x * 16;
    int ko0 = blockIdx.y * 32 + w * 4;

    float acc[16][4];
    #pragma unroll
    for (int i = 0; i < 16; i++)
        #pragma unroll
        for (int q = 0; q < 4; q++) acc[i][q] = 0.f;

    int nIter = (J/4 + 31) / 32;
    for (int it = 0; it < nIter; ++it) {
        int j = it*128 + lane*4;
        bool jv = (j < J);
        float4 wv[4];
        #pragma unroll
        for (int q = 0; q < 4; q++) {
            int ko = ko0 + q;
            if (jv && ko < KO) wv[q] = *(const float4*)&Wm[(size_t)ko*J + j];
            else               wv[q] = make_float4(0.f,0.f,0.f,0.f);
        }
        #pragma unroll
        for (int bl = 0; bl < 16; ++bl) {
            float4 xv = jv ? *(const float4*)&X[(size_t)(b0+bl)*J + j]
                           : make_float4(0.f,0.f,0.f,0.f);
            #pragma unroll
            for (int q = 0; q < 4; q++) {
                acc[bl][q] += xv.x*wv[q].x + xv.y*wv[q].y
                            + xv.z*wv[q].z + xv.w*wv[q].w;
            }
        }
    }
    // butterfly reduce across the warp (every lane ends with the full sum)
    #pragma unroll
    for (int bl = 0; bl < 16; ++bl)
        #pragma unroll
        for (int q = 0; q < 4; q++) {
            float v = acc[bl][q];
            #pragma unroll
            for (int off = 16; off; off >>= 1)
                v += __shfl_xor_sync(0xffffffffu, v, off);
            acc[bl][q] = v;
        }

    float* dst    = (mode == 0) ? g_c : outp;
    int    dstrd  = (mode == 0) ? CPAD : ostride;
    #pragma unroll
    for (int a = 0; a < 64; ++a) {
        if (lane == (a & 31)) {
            int bl = a >> 2, q = a & 3;
            int ko = ko0 + q;
            if (ko < KO) {
                float v = acc[bl][q];
                if (mode == 0) v = fmaxf(v + bias[ko], 0.f) * watt[ko];
                else           v = v + bias[ko];
                dst[(size_t)(b0+bl)*dstrd + ko] = v;
            }
        }
    }
}

// ============================================================
// Kernel 3: the big one.
// z[m,k] = sum_c input_v[b,c,s] * Wc[k,c]      (m = b*196+s)
// partial[kt][m] = sum_{k in tile} relu(z + bc[k]) * g_c[b][k]
// 128x128x8 tiles, 8x8 per thread, double-buffered smem.
// grid = (10 ktiles, 392 mtiles), 256 threads.
// ============================================================
__global__ __launch_bounds__(256, 2) void conv_logits(
    const float* __restrict__ V,
    const float* __restrict__ Wc,
    const float* __restrict__ bc)
{
    __shared__ float As[2][8][132];
    __shared__ float Bs[2][8][132];
    __shared__ float biass[128];
    __shared__ float csh[2][128];
    __shared__ float red[128][17];

    int t  = threadIdx.x;
    int kt = blockIdx.x;     // 0..9
    int mt = blockIdx.y;     // 0..391
    int tx = t & 15, ty = t >> 4;

    // ---- A (input_v) load coords: per thread 1 m-row, 4 c's ----
    int ml   = t & 127;
    int m    = mt*128 + ml;
    int bA   = m / WH_;
    int sA   = m - bA*WH_;
    size_t abase = (size_t)bA * DV_ * WH_ + sA;
    int c_hi = t >> 7;       // 0 or 1

    // ---- B (W_conv) load coords: per thread 1 c, 4 k's ----
    int cB  = t & 7;
    int kB0 = t >> 3;        // + 32*r
    int kglob[4]; bool kok[4];
    #pragma unroll
    for (int r = 0; r < 4; r++) {
        kglob[r] = kt*128 + kB0 + 32*r;
        kok[r]   = (kglob[r] < DATT_);
    }

    // ---- bias + c tiles ----
    if (t < 128) {
        int k = kt*128 + t;
        biass[t] = (k < DATT_) ? bc[k] : 0.f;
    }
    int b0 = (mt*128) / WH_;
    {
        int half = t >> 7;
        int kk   = t & 127;
        int bb   = min(b0 + half, B_-1);
        csh[half][kk] = g_c[(size_t)bb*CPAD + kt*128 + kk];
    }

    float acc[8][8];
    #pragma unroll
    for (int i = 0; i < 8; i++)
        #pragma unroll
        for (int j = 0; j < 8; j++) acc[i][j] = 0.f;

    float av[4], bv[4];
    // prologue: ct = 0
    #pragma unroll
    for (int r = 0; r < 4; r++) {
        int cl = c_hi + 2*r;
        av[r] = V[abase + (size_t)cl * WH_];
        bv[r] = kok[r] ? Wc[(size_t)kglob[r]*DV_ + cB] : 0.f;
    }
    #pragma unroll
    for (int r = 0; r < 4; r++) {
        As[0][c_hi + 2*r][ml]       = av[r];
        Bs[0][cB][kB0 + 32*r]       = bv[r];
    }
    __syncthreads();

    int buf = 0;
    for (int ct = 0; ct < DV_/8; ++ct) {
        bool hasNext = (ct + 1) < DV_/8;
        if (hasNext) {
            int cbase = (ct+1)*8;
            #pragma unroll
            for (int r = 0; r < 4; r++) {
                int cl = c_hi + 2*r;
                av[r] = V[abase + (size_t)(cbase + cl) * WH_];
                bv[r] = kok[r] ? Wc[(size_t)kglob[r]*DV_ + cbase + cB] : 0.f;
            }
        }
        #pragma unroll
        for (int kk = 0; kk < 8; ++kk) {
            float4 a0 = *(const float4*)&As[buf][kk][ty*8];
            float4 a1 = *(const float4*)&As[buf][kk][ty*8 + 4];
            float4 p0 = *(const float4*)&Bs[buf][kk][tx*8];
            float4 p1 = *(const float4*)&Bs[buf][kk][tx*8 + 4];
            float afr[8] = {a0.x,a0.y,a0.z,a0.w,a1.x,a1.y,a1.z,a1.w};
            float bfr[8] = {p0.x,p0.y,p0.z,p0.w,p1.x,p1.y,p1.z,p1.w};
            #pragma unroll
            for (int i = 0; i < 8; i++)
                #pragma unroll
                for (int j = 0; j < 8; j++)
                    acc[i][j] += afr[i] * bfr[j];
        }
        if (hasNext) {
            int nb = buf ^ 1;
            #pragma unroll
            for (int r = 0; r < 4; r++) {
                As[nb][c_hi + 2*r][ml] = av[r];
                Bs[nb][cB][kB0 + 32*r] = bv[r];
            }
        }
        __syncthreads();
        buf ^= 1;
    }

    // ---- epilogue: relu(z+bias)*c, reduce over k-tile ----
    #pragma unroll
    for (int i = 0; i < 8; i++) {
        int mrow = ty*8 + i;
        int mm   = mt*128 + mrow;
        int bb   = mm / WH_;
        int rsel = bb - b0;        // 0 or 1
        float r = 0.f;
        #pragma unroll
        for (int j = 0; j < 8; j++) {
            int kl = tx*8 + j;
            r += fmaxf(acc[i][j] + biass[kl], 0.f) * csh[rsel][kl];
        }
        red[mrow][tx] = r;
    }
    __syncthreads();
    if (t < 128) {
        float s = 0.f;
        #pragma unroll
        for (int x = 0; x < 16; x++) s += red[t][x];
        g_lpart[(size_t)kt*M_ + mt*128 + t] = s;
    }
}

// ============================================================
// Kernel 4: logits -> softmax -> attention-weighted sum of input_v
// grid (8 dchunks, 256 batches), 256 threads
// ============================================================
__global__ __launch_bounds__(256) void attn_kernel(
    const float* __restrict__ V, const float* __restrict__ batt)
{
    __shared__ float sm[256];
    __shared__ float attn[WH_];
    int b = blockIdx.y;
    int t = threadIdx.x;

    float v = -3.4e38f;
    if (t < WH_) {
        float s = batt[0];
        #pragma unroll
        for (int kt = 0; kt < NKT; ++kt)
            s += g_lpart[(size_t)kt*M_ + b*WH_ + t];
        v = s;
    }
    sm[t] = v;
    __syncthreads();
    for (int off = 128; off; off >>= 1) {
        if (t < off) sm[t] = fmaxf(sm[t], sm[t + off]);
        __syncthreads();
    }
    float mx = sm[0];
    __syncthreads();
    float e = (t < WH_) ? expf(v - mx) : 0.f;
    sm[t] = e;
    __syncthreads();
    for (int off = 128; off; off >>= 1) {
        if (t < off) sm[t] += sm[t + off];
        __syncthreads();
    }
    float inv = 1.f / sm[0];
    if (t < WH_) attn[t] = e * inv;
    __syncthreads();

    int d = blockIdx.x * 256 + t;
    const float4* row = (const float4*)&V[((size_t)b*DV_ + d) * WH_];
    float acc = 0.f;
    #pragma unroll
    for (int s4 = 0; s4 < WH_/4; ++s4) {
        float4 x = row[s4];
        acc += x.x*attn[4*s4] + x.y*attn[4*s4+1]
             + x.z*attn[4*s4+2] + x.w*attn[4*s4+3];
    }
    g_xvatt[(size_t)b*DV_ + d] = acc;
}

// ============================================================
extern "C" void kernel_launch(void* const* d_in, const int* in_sizes, int n_in,
                              void* d_out, int out_size)
{
    const float* input_v = (const float*)d_in[0];
    const float* emb     = (const float*)d_in[1];
    const float* W_conv  = (const float*)d_in[2];
    const float* b_conv  = (const float*)d_in[3];
    const float* W_lin_a = (const float*)d_in[4];
    const float* b_lin_a = (const float*)d_in[5];
    const float* w_att   = (const float*)d_in[6];
    const float* b_att   = (const float*)d_in[7];
    const float* W_img   = (const float*)d_in[8];
    const float* b_img   = (const float*)d_in[9];
    const float* W_ans   = (const float*)d_in[10];
    const float* b_ans   = (const float*)d_in[11];
    const int*   input_a = (const int*)d_in[12];
    float* out = (float*)d_out;

    // 1. gather embeddings + pad c
    init_kernel<<<620, 256>>>(emb, input_a);
    // 2. c[b,k] = relu(xa . W_lin_a^T + b) * w_att
    small_gemm<<<dim3(16, (DATT_+31)/32), 256>>>(
        0, DA_, W_lin_a, DATT_, b_lin_a, w_att, nullptr, 0, 0);
    // 3. fused conv1x1 + relu + weighted k-reduction -> logit partials
    conv_logits<<<dim3(NKT, M_/128), 256>>>(input_v, W_conv, b_conv);
    // 4. softmax + attention-weighted sum over spatial dim
    attn_kernel<<<dim3(DV_/256, B_), 256>>>(input_v, b_att);
    // 5. v_feat = xvatt . W_img^T + b_img  -> out[:, 0:1024]
    small_gemm<<<dim3(16, DOUT_/32), 256>>>(
        1, DV_, W_img, DOUT_, b_img, nullptr, out, 2*DOUT_, 1);
    // 6. a_feat = xavec . W_ans^T + b_ans -> out[:, 1024:2048]
    small_gemm<<<dim3(16, DOUT_/32), 256>>>(
        0, DA_, W_ans, DOUT_, b_ans, nullptr, out + DOUT_, 2*DOUT_, 1);
}

// round 2
// speedup vs baseline: 1.0005x; 1.0005x over previous
#include <cuda_runtime.h>
#include <math.h>

#define B_    256
#define DV_   2048
#define WH_   196
#define DA_   620
#define DATT_ 1200
#define DOUT_ 1024
#define M_    (B_*WH_)   // 50176 = 392*128
#define CPAD  1280       // DATT padded to 10*128
#define NKT   10         // k tiles of 128

// ---- device scratch (no allocs allowed) ----
__device__ float g_xavec[B_*DA_];     // gathered answer embeddings [256][620]
__device__ float g_c[B_*CPAD];        // x_a * w_att, zero-padded    [256][1280]
__device__ float g_lpart[NKT*M_];     // per-ktile logit partials
__device__ float g_xvatt[B_*DV_];     // attention-weighted visual   [256][2048]

// ============================================================
// Kernel 1: gather embeddings + zero-pad g_c tail columns
// ============================================================
__global__ __launch_bounds__(256) void init_kernel(
    const float* __restrict__ emb, const int* __restrict__ ia)
{
    int gid = blockIdx.x * 256 + threadIdx.x;
    if (gid < B_*DA_) {
        int b = gid / DA_;
        int j = gid - b * DA_;
        g_xavec[gid] = emb[(size_t)ia[b] * DA_ + j];
    }
    if (gid < B_*(CPAD-DATT_)) {
        int b = gid / (CPAD-DATT_);
        int j = gid - b * (CPAD-DATT_);
        g_c[b*CPAD + DATT_ + j] = 0.f;
    }
}

// ============================================================
// Kernel 2/5/6: small GEMM  out[b][ko] = X[b,:J] . Wm[ko,:J]
// block = 16 batches x 32 ko (8 warps x 4 ko each)
// xsel: 0 -> g_xavec (J=620), 1 -> g_xvatt (J=2048)
// mode: 0 -> g_c = relu(acc+bias)*watt   1 -> out = acc+bias
// ============================================================
__global__ __launch_bounds__(256) void small_gemm(
    int xsel, int J,
    const float* __restrict__ Wm, int KO,
    const float* __restrict__ bias,
    const float* __restrict__ watt,
    float* __restrict__ outp, int ostride, int mode)
{
    const float* X = xsel ? g_xvatt : g_xavec;
    int t = threadIdx.x, lane = t & 31, w = t >> 5;
    int b0  = blockIdx.x * 16;
    int ko0 = blockIdx.y * 32 + w * 4;

    float acc[16][4];
    #pragma unroll
    for (int i = 0; i < 16; i++)
        #pragma unroll
        for (int q = 0; q < 4; q++) acc[i][q] = 0.f;

    int nIter = (J/4 + 31) / 32;
    for (int it = 0; it < nIter; ++it) {
        int j = it*128 + lane*4;
        bool jv = (j < J);
        float4 wv[4];
        #pragma unroll
        for (int q = 0; q < 4; q++) {
            int ko = ko0 + q;
            if (jv && ko < KO) wv[q] = *(const float4*)&Wm[(size_t)ko*J + j];
            else               wv[q] = make_float4(0.f,0.f,0.f,0.f);
        }
        #pragma unroll
        for (int bl = 0; bl < 16; ++bl) {
            float4 xv = jv ? *(const float4*)&X[(size_t)(b0+bl)*J + j]
                           : make_float4(0.f,0.f,0.f,0.f);
            #pragma unroll
            for (int q = 0; q < 4; q++) {
                acc[bl][q] += xv.x*wv[q].x + xv.y*wv[q].y
                            + xv.z*wv[q].z + xv.w*wv[q].w;
            }
        }
    }
    // butterfly reduce across the warp (every lane ends with the full sum)
    #pragma unroll
    for (int bl = 0; bl < 16; ++bl)
        #pragma unroll
        for (int q = 0; q < 4; q++) {
            float v = acc[bl][q];
            #pragma unroll
            for (int off = 16; off; off >>= 1)
                v += __shfl_xor_sync(0xffffffffu, v, off);
            acc[bl][q] = v;
        }

    float* dst    = (mode == 0) ? g_c : outp;
    int    dstrd  = (mode == 0) ? CPAD : ostride;
    #pragma unroll
    for (int a = 0; a < 64; ++a) {
        if (lane == (a & 31)) {
            int bl = a >> 2, q = a & 3;
            int ko = ko0 + q;
            if (ko < KO) {
                float v = acc[bl][q];
                if (mode == 0) v = fmaxf(v + bias[ko], 0.f) * watt[ko];
                else           v = v + bias[ko];
                dst[(size_t)(b0+bl)*dstrd + ko] = v;
            }
        }
    }
}

// ============================================================
// Kernel 3: the big one.
// z[m,k] = sum_c input_v[b,c,s] * Wc[k,c]      (m = b*196+s)
// partial[kt][m] = sum_{k in tile} relu(z + bc[k]) * g_c[b][k]
// 128x128x8 tiles, 8x8 per thread, double-buffered smem.
// grid = (10 ktiles, 392 mtiles), 256 threads.
// ============================================================
__global__ __launch_bounds__(256, 2) void conv_logits(
    const float* __restrict__ V,
    const float* __restrict__ Wc,
    const float* __restrict__ bc)
{
    __shared__ float As[2][8][132];
    __shared__ float Bs[2][8][132];
    __shared__ float biass[128];
    __shared__ float csh[2][128];
    __shared__ float red[128][17];

    int t  = threadIdx.x;
    int kt = blockIdx.x;     // 0..9
    int mt = blockIdx.y;     // 0..391
    int tx = t & 15, ty = t >> 4;

    // ---- A (input_v) load coords: per thread 1 m-row, 4 c's ----
    int ml   = t & 127;
    int m    = mt*128 + ml;
    int bA   = m / WH_;
    int sA   = m - bA*WH_;
    size_t abase = (size_t)bA * DV_ * WH_ + sA;
    int c_hi = t >> 7;       // 0 or 1

    // ---- B (W_conv) load coords: per thread 1 c, 4 k's ----
    int cB  = t & 7;
    int kB0 = t >> 3;        // + 32*r
    int kglob[4]; bool kok[4];
    #pragma unroll
    for (int r = 0; r < 4; r++) {
        kglob[r] = kt*128 + kB0 + 32*r;
        kok[r]   = (kglob[r] < DATT_);
    }

    // ---- bias + c tiles ----
    if (t < 128) {
        int k = kt*128 + t;
        biass[t] = (k < DATT_) ? bc[k] : 0.f;
    }
    int b0 = (mt*128) / WH_;
    {
        int half = t >> 7;
        int kk   = t & 127;
        int bb   = min(b0 + half, B_-1);
        csh[half][kk] = g_c[(size_t)bb*CPAD + kt*128 + kk];
    }

    float acc[8][8];
    #pragma unroll
    for (int i = 0; i < 8; i++)
        #pragma unroll
        for (int j = 0; j < 8; j++) acc[i][j] = 0.f;

    float av[4], bv[4];
    // prologue: ct = 0
    #pragma unroll
    for (int r = 0; r < 4; r++) {
        int cl = c_hi + 2*r;
        av[r] = V[abase + (size_t)cl * WH_];
        bv[r] = kok[r] ? Wc[(size_t)kglob[r]*DV_ + cB] : 0.f;
    }
    #pragma unroll
    for (int r = 0; r < 4; r++) {
        As[0][c_hi + 2*r][ml]       = av[r];
        Bs[0][cB][kB0 + 32*r]       = bv[r];
    }
    __syncthreads();

    int buf = 0;
    for (int ct = 0; ct < DV_/8; ++ct) {
        bool hasNext = (ct + 1) < DV_/8;
        if (hasNext) {
            int cbase = (ct+1)*8;
            #pragma unroll
            for (int r = 0; r < 4; r++) {
                int cl = c_hi + 2*r;
                av[r] = V[abase + (size_t)(cbase + cl) * WH_];
                bv[r] = kok[r] ? Wc[(size_t)kglob[r]*DV_ + cbase + cB] : 0.f;
            }
        }
        #pragma unroll
        for (int kk = 0; kk < 8; ++kk) {
            float4 a0 = *(const float4*)&As[buf][kk][ty*8];
            float4 a1 = *(const float4*)&As[buf][kk][ty*8 + 4];
            float4 p0 = *(const float4*)&Bs[buf][kk][tx*8];
            float4 p1 = *(const float4*)&Bs[buf][kk][tx*8 + 4];
            float afr[8] = {a0.x,a0.y,a0.z,a0.w,a1.x,a1.y,a1.z,a1.w};
            float bfr[8] = {p0.x,p0.y,p0.z,p0.w,p1.x,p1.y,p1.z,p1.w};
            #pragma unroll
            for (int i = 0; i < 8; i++)
                #pragma unroll
                for (int j = 0; j < 8; j++)
                    acc[i][j] += afr[i] * bfr[j];
        }
        if (hasNext) {
            int nb = buf ^ 1;
            #pragma unroll
            for (int r = 0; r < 4; r++) {
                As[nb][c_hi + 2*r][ml] = av[r];
                Bs[nb][cB][kB0 + 32*r] = bv[r];
            }
        }
        __syncthreads();
        buf ^= 1;
    }

    // ---- epilogue: relu(z+bias)*c, reduce over k-tile ----
    #pragma unroll
    for (int i = 0; i < 8; i++) {
        int mrow = ty*8 + i;
        int mm   = mt*128 + mrow;
        int bb   = mm / WH_;
        int rsel = bb - b0;        // 0 or 1
        float r = 0.f;
        #pragma unroll
        for (int j = 0; j < 8; j++) {
            int kl = tx*8 + j;
            r += fmaxf(acc[i][j] + biass[kl], 0.f) * csh[rsel][kl];
        }
        red[mrow][tx] = r;
    }
    __syncthreads();
    if (t < 128) {
        float s = 0.f;
        #pragma unroll
        for (int x = 0; x < 16; x++) s += red[t][x];
        g_lpart[(size_t)kt*M_ + mt*128 + t] = s;
    }
}

// ============================================================
// Kernel 4: logits -> softmax -> attention-weighted sum of input_v
// grid (8 dchunks, 256 batches), 256 threads
// ============================================================
__global__ __launch_bounds__(256) void attn_kernel(
    const float* __restrict__ V, const float* __restrict__ batt)
{
    __shared__ float sm[256];
    __shared__ float attn[WH_];
    int b = blockIdx.y;
    int t = threadIdx.x;

    float v = -3.4e38f;
    if (t < WH_) {
        float s = batt[0];
        #pragma unroll
        for (int kt = 0; kt < NKT; ++kt)
            s += g_lpart[(size_t)kt*M_ + b*WH_ + t];
        v = s;
    }
    sm[t] = v;
    __syncthreads();
    for (int off = 128; off; off >>= 1) {
        if (t < off) sm[t] = fmaxf(sm[t], sm[t + off]);
        __syncthreads();
    }
    float mx = sm[0];
    __syncthreads();
    float e = (t < WH_) ? expf(v - mx) : 0.f;
    sm[t] = e;
    __syncthreads();
    for (int off = 128; off; off >>= 1) {
        if (t < off) sm[t] += sm[t + off];
        __syncthreads();
    }
    float inv = 1.f / sm[0];
    if (t < WH_) attn[t] = e * inv;
    __syncthreads();

    int d = blockIdx.x * 256 + t;
    const float4* row = (const float4*)&V[((size_t)b*DV_ + d) * WH_];
    float acc = 0.f;
    #pragma unroll
    for (int s4 = 0; s4 < WH_/4; ++s4) {
        float4 x = row[s4];
        acc += x.x*attn[4*s4] + x.y*attn[4*s4+1]
             + x.z*attn[4*s4+2] + x.w*attn[4*s4+3];
    }
    g_xvatt[(size_t)b*DV_ + d] = acc;
}

// ============================================================
extern "C" void kernel_launch(void* const* d_in, const int* in_sizes, int n_in,
                              void* d_out, int out_size)
{
    const float* input_v = (const float*)d_in[0];
    const float* emb     = (const float*)d_in[1];
    const float* W_conv  = (const float*)d_in[2];
    const float* b_conv  = (const float*)d_in[3];
    const float* W_lin_a = (const float*)d_in[4];
    const float* b_lin_a = (const float*)d_in[5];
    const float* w_att   = (const float*)d_in[6];
    const float* b_att   = (const float*)d_in[7];
    const float* W_img   = (const float*)d_in[8];
    const float* b_img   = (const float*)d_in[9];
    const float* W_ans   = (const float*)d_in[10];
    const float* b_ans   = (const float*)d_in[11];
    const int*   input_a = (const int*)d_in[12];
    float* out = (float*)d_out;

    // 1. gather embeddings + pad c
    init_kernel<<<620, 256>>>(emb, input_a);
    // 2. c[b,k] = relu(xa . W_lin_a^T + b) * w_att
    small_gemm<<<dim3(16, (DATT_+31)/32), 256>>>(
        0, DA_, W_lin_a, DATT_, b_lin_a, w_att, nullptr, 0, 0);
    // 3. fused conv1x1 + relu + weighted k-reduction -> logit partials
    conv_logits<<<dim3(NKT, M_/128), 256>>>(input_v, W_conv, b_conv);
    // 4. softmax + attention-weighted sum over spatial dim
    attn_kernel<<<dim3(DV_/256, B_), 256>>>(input_v, b_att);
    // 5. v_feat = xvatt . W_img^T + b_img  -> out[:, 0:1024]
    small_gemm<<<dim3(16, DOUT_/32), 256>>>(
        1, DV_, W_img, DOUT_, b_img, nullptr, out, 2*DOUT_, 1);
    // 6. a_feat = xavec . W_ans^T + b_ans -> out[:, 1024:2048]
    small_gemm<<<dim3(16, DOUT_/32), 256>>>(
        0, DA_, W_ans, DOUT_, b_ans, nullptr, out + DOUT_, 2*DOUT_, 1);
}

// round 4
// speedup vs baseline: 3.6036x; 3.6017x over previous
#include <cuda_runtime.h>
#include <math.h>
#include <stdint.h>

#define B_    256
#define DV_   2048
#define WH_   196
#define DA_   620
#define DATT_ 1200
#define DOUT_ 1024
#define M_    (B_*WH_)     // 50176 = 392*128
#define CPAD  1280
#define NPAD  1280
#define NKT   10           // n-tile blocks of 128 (like round 1 k-tiles)

#define RS    36           // smem row stride (floats) for 32-k chunk
#define STG_F (128*RS*2)   // floats per stage (A + B) = 9216
#define NSTG  3
#define DSMEM (NSTG*STG_F*4)   // 110592 bytes

// ---- device scratch ----
__device__ float g_xavec[B_*DA_];
__device__ float g_c[B_*CPAD];
__device__ float g_lpart[NKT*M_];
__device__ float g_xvatt[B_*DV_];
__device__ float g_At[(size_t)M_*DV_];
__device__ float g_Wt[(size_t)NPAD*DV_];

// ================= helpers =================
__device__ __forceinline__ uint32_t smem_u32(const void* p){
    uint32_t a;
    asm("{ .reg .u64 t; cvta.to.shared.u64 t, %1; cvt.u32.u64 %0, t; }" : "=r"(a) : "l"(p));
    return a;
}
__device__ __forceinline__ float to_tf32(float x){
    float r; asm("cvt.rna.tf32.f32 %0, %1;" : "=f"(r) : "f"(x));
    return r;
}
__device__ __forceinline__ void cpa16(uint32_t d, const float* s){
    asm volatile("cp.async.cg.shared.global [%0], [%1], 16;" :: "r"(d), "l"(s) : "memory");
}
__device__ __forceinline__ void ldm4(uint32_t a, uint32_t& r0, uint32_t& r1,
                                     uint32_t& r2, uint32_t& r3){
    asm volatile("ldmatrix.sync.aligned.m8n8.x4.shared.b16 {%0,%1,%2,%3}, [%4];"
        : "=r"(r0), "=r"(r1), "=r"(r2), "=r"(r3) : "r"(a));
}
__device__ __forceinline__ void mma_tf32(float* c, uint32_t a0, uint32_t a1,
                                         uint32_t a2, uint32_t a3,
                                         uint32_t b0, uint32_t b1){
    asm volatile(
        "mma.sync.aligned.m16n8k8.row.col.f32.tf32.tf32.f32 "
        "{%0,%1,%2,%3}, {%4,%5,%6,%7}, {%8,%9}, {%0,%1,%2,%3};"
        : "+f"(c[0]), "+f"(c[1]), "+f"(c[2]), "+f"(c[3])
        : "r"(a0), "r"(a1), "r"(a2), "r"(a3), "r"(b0), "r"(b1));
}

// ================= prep kernels =================
__global__ __launch_bounds__(256) void init_kernel(
    const float* __restrict__ emb, const int* __restrict__ ia)
{
    int gid = blockIdx.x * 256 + threadIdx.x;
    if (gid < B_*DA_) {
        int b = gid / DA_;
        int j = gid - b * DA_;
        g_xavec[gid] = emb[(size_t)ia[b] * DA_ + j];
    }
    if (gid < B_*(CPAD-DATT_)) {
        int b = gid / (CPAD-DATT_);
        int j = gid - b * (CPAD-DATT_);
        g_c[b*CPAD + DATT_ + j] = 0.f;
    }
}

__global__ __launch_bounds__(256) void round_w(const float* __restrict__ W)
{
    int i = blockIdx.x*256 + threadIdx.x;        // over 655360 float4
    float4 v = make_float4(0.f,0.f,0.f,0.f);
    if (i < (DATT_*DV_)/4) {
        v = ((const float4*)W)[i];
        v.x = to_tf32(v.x); v.y = to_tf32(v.y);
        v.z = to_tf32(v.z); v.w = to_tf32(v.w);
    }
    ((float4*)g_Wt)[i] = v;
}

__global__ __launch_bounds__(256) void transpose_k(const float* __restrict__ V)
{
    __shared__ float tile[32][33];
    int tx = threadIdx.x & 31, ty = threadIdx.x >> 5;
    int c0 = blockIdx.x * 32;
    int s0 = blockIdx.y * 32;
    int b  = blockIdx.z;
    const float* src = V + (size_t)b*DV_*WH_;
    #pragma unroll
    for (int i = 0; i < 4; i++) {
        int c = c0 + ty + i*8, s = s0 + tx;
        if (s < WH_) tile[ty + i*8][tx] = src[(size_t)c*WH_ + s];
    }
    __syncthreads();
    #pragma unroll
    for (int i = 0; i < 4; i++) {
        int s = s0 + ty + i*8, c = c0 + tx;
        if (s < WH_)
            g_At[((size_t)b*WH_ + s)*DV_ + c] = to_tf32(tile[tx][ty + i*8]);
    }
}

// ================= small GEMM =================
__global__ __launch_bounds__(256) void small_gemm(
    int xsel, int J, const float* __restrict__ Wm, int KO,
    const float* __restrict__ bias, const float* __restrict__ watt,
    float* __restrict__ outp, int ostride, int mode)
{
    const float* X = xsel ? g_xvatt : g_xavec;
    int t = threadIdx.x, lane = t & 31, w = t >> 5;
    int b0  = blockIdx.x * 16;
    int ko0 = blockIdx.y * 32 + w * 4;

    float acc[16][4];
    #pragma unroll
    for (int i = 0; i < 16; i++)
        #pragma unroll
        for (int q = 0; q < 4; q++) acc[i][q] = 0.f;

    int nIter = (J/4 + 31) / 32;
    for (int it = 0; it < nIter; ++it) {
        int j = it*128 + lane*4;
        bool jv = (j < J);
        float4 wv[4];
        #pragma unroll
        for (int q = 0; q < 4; q++) {
            int ko = ko0 + q;
            if (jv && ko < KO) wv[q] = *(const float4*)&Wm[(size_t)ko*J + j];
            else               wv[q] = make_float4(0.f,0.f,0.f,0.f);
        }
        #pragma unroll
        for (int bl = 0; bl < 16; ++bl) {
            float4 xv = jv ? *(const float4*)&X[(size_t)(b0+bl)*J + j]
                           : make_float4(0.f,0.f,0.f,0.f);
            #pragma unroll
            for (int q = 0; q < 4; q++)
                acc[bl][q] += xv.x*wv[q].x + xv.y*wv[q].y + xv.z*wv[q].z + xv.w*wv[q].w;
        }
    }
    #pragma unroll
    for (int bl = 0; bl < 16; ++bl)
        #pragma unroll
        for (int q = 0; q < 4; q++) {
            float v = acc[bl][q];
            #pragma unroll
            for (int off = 16; off; off >>= 1)
                v += __shfl_xor_sync(0xffffffffu, v, off);
            acc[bl][q] = v;
        }
    float* dst   = (mode == 0) ? g_c : outp;
    int    dstrd = (mode == 0) ? CPAD : ostride;
    #pragma unroll
    for (int a = 0; a < 64; ++a) {
        if (lane == (a & 31)) {
            int bl = a >> 2, q = a & 3;
            int ko = ko0 + q;
            if (ko < KO) {
                float v = acc[bl][q];
                if (mode == 0) v = fmaxf(v + bias[ko], 0.f) * watt[ko];
                else           v = v + bias[ko];
                dst[(size_t)(b0+bl)*dstrd + ko] = v;
            }
        }
    }
}

// ================= tf32 mma.sync GEMM + fused logit reduction =================
// grid (10 ntiles, 392 mtiles), 256 threads, 128x128x32 tiles, 3-stage cp.async.
__global__ __launch_bounds__(256, 2) void conv_mma(const float* __restrict__ bc)
{
    extern __shared__ float sm[];
    __shared__ float bias_s[128];
    __shared__ float csh[2][128];
    __shared__ float red[4][128];

    int t = threadIdx.x, lane = t & 31, w = t >> 5;
    int wm = w & 1, wn = w >> 1;
    int nt = blockIdx.x, mt = blockIdx.y;
    int m0 = mt*128, n0 = nt*128;
    int b0 = m0 / WH_;

    // epilogue constants
    if (t < 128) {
        int k = n0 + t;
        bias_s[t] = (k < DATT_) ? bc[k] : 0.f;
        csh[0][t] = g_c[(size_t)b0*CPAD + k];
        csh[1][t] = g_c[(size_t)min(b0+1, B_-1)*CPAD + k];
    }

    uint32_t smu = smem_u32(sm);

    // ---- stage loader: 8 cp.async.16 per thread ----
    auto load_stage = [&](int s, int kc) {
        int k0 = kc*32;
        uint32_t base = smu + (uint32_t)s*STG_F*4;
        #pragma unroll
        for (int j = 0; j < 4; j++) {
            int e = j*256 + t;          // 0..1023
            int row = e >> 3, c16 = e & 7;
            cpa16(base + (uint32_t)(row*RS + c16*4)*4,
                  g_At + (size_t)(m0+row)*DV_ + k0 + c16*4);
            cpa16(base + (uint32_t)(128*RS + row*RS + c16*4)*4,
                  g_Wt + (size_t)(n0+row)*DV_ + k0 + c16*4);
        }
    };

    float acc[4][4][4];
    #pragma unroll
    for (int i = 0; i < 4; i++)
        #pragma unroll
        for (int j = 0; j < 4; j++)
            #pragma unroll
            for (int q = 0; q < 4; q++) acc[i][j][q] = 0.f;

    load_stage(0, 0);
    asm volatile("cp.async.commit_group;" ::: "memory");
    load_stage(1, 1);
    asm volatile("cp.async.commit_group;" ::: "memory");

    int jrow = lane & 7;         // ldmatrix row supplied by this thread
    int jmat = lane >> 3;        // which 8x8 matrix (0..3)

    for (int i = 0; i < DV_/32; ++i) {
        asm volatile("cp.async.wait_group 1;" ::: "memory");
        __syncthreads();
        if (i + 2 < DV_/32) load_stage((i+2) % NSTG, i+2);
        asm volatile("cp.async.commit_group;" ::: "memory");

        uint32_t abase = smu + (uint32_t)(i % NSTG)*STG_F*4;
        uint32_t bbase = abase + 128u*RS*4;

        #pragma unroll
        for (int ks = 0; ks < 4; ++ks) {
            uint32_t a[4][4], b[2][4];
            // A frags: matrices {rows+0 k0, rows+8 k0, rows+0 k4, rows+8 k4}
            #pragma unroll
            for (int mt4 = 0; mt4 < 4; ++mt4) {
                int r = wm*64 + mt4*16 + jrow + (jmat & 1)*8;
                int c = ks*8 + (jmat >> 1)*4;
                ldm4(abase + (uint32_t)(r*RS + c)*4,
                     a[mt4][0], a[mt4][1], a[mt4][2], a[mt4][3]);
            }
            // B frags: matrices {n+0 k0, n+0 k4, n+8 k0, n+8 k4} -> 2 ntiles each
            #pragma unroll
            for (int np = 0; np < 2; ++np) {
                int r = wn*32 + np*16 + jrow + (jmat >> 1)*8;
                int c = ks*8 + (jmat & 1)*4;
                ldm4(bbase + (uint32_t)(r*RS + c)*4,
                     b[np][0], b[np][1], b[np][2], b[np][3]);
            }
            #pragma unroll
            for (int mt4 = 0; mt4 < 4; ++mt4) {
                #pragma unroll
                for (int nt4 = 0; nt4 < 4; ++nt4) {
                    uint32_t bb0 = b[nt4>>1][(nt4&1)*2];
                    uint32_t bb1 = b[nt4>>1][(nt4&1)*2 + 1];
                    mma_tf32(acc[mt4][nt4],
                             a[mt4][0], a[mt4][1], a[mt4][2], a[mt4][3],
                             bb0, bb1);
                }
            }
        }
        __syncthreads();
    }

    // ---- epilogue: relu(z+bias)*c, reduce over n ----
    #pragma unroll
    for (int mt4 = 0; mt4 < 4; ++mt4) {
        int lm0 = wm*64 + mt4*16 + (lane >> 2);
        int rs0 = (m0 + lm0) / WH_ - b0;
        int rs1 = (m0 + lm0 + 8) / WH_ - b0;
        float s0 = 0.f, s1 = 0.f;
        #pragma unroll
        for (int nt4 = 0; nt4 < 4; ++nt4) {
            int ln = wn*32 + nt4*8 + 2*(lane & 3);
            float bv0 = bias_s[ln], bv1 = bias_s[ln+1];
            s0 += fmaxf(acc[mt4][nt4][0] + bv0, 0.f) * csh[rs0][ln]
                + fmaxf(acc[mt4][nt4][1] + bv1, 0.f) * csh[rs0][ln+1];
            s1 += fmaxf(acc[mt4][nt4][2] + bv0, 0.f) * csh[rs1][ln]
                + fmaxf(acc[mt4][nt4][3] + bv1, 0.f) * csh[rs1][ln+1];
        }
        s0 += __shfl_xor_sync(0xffffffffu, s0, 1);
        s0 += __shfl_xor_sync(0xffffffffu, s0, 2);
        s1 += __shfl_xor_sync(0xffffffffu, s1, 1);
        s1 += __shfl_xor_sync(0xffffffffu, s1, 2);
        if ((lane & 3) == 0) {
            red[wn][lm0]     = s0;
            red[wn][lm0 + 8] = s1;
        }
    }
    __syncthreads();
    if (t < 128)
        g_lpart[(size_t)nt*M_ + m0 + t]
            = red[0][t] + red[1][t] + red[2][t] + red[3][t];
}

// ================= softmax + weighted sum =================
__global__ __launch_bounds__(256) void attn_kernel(
    const float* __restrict__ V, const float* __restrict__ batt)
{
    __shared__ float sm[256];
    __shared__ float attn[WH_];
    int b = blockIdx.y;
    int t = threadIdx.x;

    float v = -3.4e38f;
    if (t < WH_) {
        float s = batt[0];
        #pragma unroll
        for (int kt = 0; kt < NKT; ++kt)
            s += g_lpart[(size_t)kt*M_ + b*WH_ + t];
        v = s;
    }
    sm[t] = v;
    __syncthreads();
    for (int off = 128; off; off >>= 1) {
        if (t < off) sm[t] = fmaxf(sm[t], sm[t + off]);
        __syncthreads();
    }
    float mx = sm[0];
    __syncthreads();
    float e = (t < WH_) ? expf(v - mx) : 0.f;
    sm[t] = e;
    __syncthreads();
    for (int off = 128; off; off >>= 1) {
        if (t < off) sm[t] += sm[t + off];
        __syncthreads();
    }
    float inv = 1.f / sm[0];
    if (t < WH_) attn[t] = e * inv;
    __syncthreads();

    int d = blockIdx.x * 256 + t;
    const float4* row = (const float4*)&V[((size_t)b*DV_ + d) * WH_];
    float acc = 0.f;
    #pragma unroll
    for (int s4 = 0; s4 < WH_/4; ++s4) {
        float4 x = row[s4];
        acc += x.x*attn[4*s4] + x.y*attn[4*s4+1]
             + x.z*attn[4*s4+2] + x.w*attn[4*s4+3];
    }
    g_xvatt[(size_t)b*DV_ + d] = acc;
}

// ============================================================
extern "C" void kernel_launch(void* const* d_in, const int* in_sizes, int n_in,
                              void* d_out, int out_size)
{
    const float* input_v = (const float*)d_in[0];
    const float* emb     = (const float*)d_in[1];
    const float* W_conv  = (const float*)d_in[2];
    const float* b_conv  = (const float*)d_in[3];
    const float* W_lin_a = (const float*)d_in[4];
    const float* b_lin_a = (const float*)d_in[5];
    const float* w_att   = (const float*)d_in[6];
    const float* b_att   = (const float*)d_in[7];
    const float* W_img   = (const float*)d_in[8];
    const float* b_img   = (const float*)d_in[9];
    const float* W_ans   = (const float*)d_in[10];
    const float* b_ans   = (const float*)d_in[11];
    const int*   input_a = (const int*)d_in[12];
    float* out = (float*)d_out;

    cudaFuncSetAttribute(conv_mma, cudaFuncAttributeMaxDynamicSharedMemorySize,
                         DSMEM);

    init_kernel<<<620, 256>>>(emb, input_a);
    round_w<<<(NPAD*DV_/4 + 255)/256, 256>>>(W_conv);
    transpose_k<<<dim3(DV_/32, (WH_+31)/32, B_), 256>>>(input_v);
    small_gemm<<<dim3(16, (DATT_+31)/32), 256>>>(
        0, DA_, W_lin_a, DATT_, b_lin_a, w_att, nullptr, 0, 0);
    conv_mma<<<dim3(NKT, M_/128), 256, DSMEM>>>(b_conv);
    attn_kernel<<<dim3(DV_/256, B_), 256>>>(input_v, b_att);
    small_gemm<<<dim3(16, DOUT_/32), 256>>>(
        1, DV_, W_img, DOUT_, b_img, nullptr, out, 2*DOUT_, 1);
    small_gemm<<<dim3(16, DOUT_/32), 256>>>(
        0, DA_, W_ans, DOUT_, b_ans, nullptr, out + DOUT_, 2*DOUT_, 1);
}